// round 1
// baseline (speedup 1.0000x reference)
#include <cuda_runtime.h>
#include <cstddef>
#include <cstdint>

#define NBATCH 32
#define SEQT   2048
#define DIN    256
#define HID    256
#define GDIM   1024   // 4*HID

// ---------------- scratch (static device allocations, allowed) ----------------
__device__ float g_xg_f[(size_t)NBATCH * SEQT * GDIM];   // 256 MB
__device__ float g_xg_r[(size_t)NBATCH * SEQT * GDIM];   // 256 MB
__device__ float g_h0 [(size_t)NBATCH * SEQT * 2 * HID]; // 128 MB

// =====================================================================
// GEMM: C[M,N] = A[M,K] @ W[N,K]^T + bias[N]
// M = 65536 (grid.y*128), N = 1024 (grid.x*128), K runtime {256,512}
// 128x128 tile, BK=16, 256 threads, 8x8 per-thread (2x2 blocks of 4x4)
// =====================================================================
__global__ __launch_bounds__(256, 2)
void sgemm_bias(const float* __restrict__ A, const float* __restrict__ W,
                const float* __restrict__ bias, float* __restrict__ C, int K)
{
    __shared__ float As[16][132];
    __shared__ float Bs[16][132];

    const int tid = threadIdx.x;
    const int tx  = tid & 15;
    const int ty  = tid >> 4;
    const size_t m0 = (size_t)blockIdx.y * 128;
    const size_t n0 = (size_t)blockIdx.x * 128;
    const int N  = gridDim.x * 128;

    // global-load mapping: each thread loads 8 consecutive k (2 float4) of one row
    const int lr = tid >> 1;          // row in tile 0..127
    const int lk = (tid & 1) * 8;     // k offset 0 or 8

    const float* Aptr = A + (m0 + lr) * (size_t)K + lk;
    const float* Wptr = W + (n0 + lr) * (size_t)K + lk;

    float4 pa0 = *(const float4*)(Aptr);
    float4 pa1 = *(const float4*)(Aptr + 4);
    float4 pw0 = *(const float4*)(Wptr);
    float4 pw1 = *(const float4*)(Wptr + 4);

    float acc[8][8];
    #pragma unroll
    for (int i = 0; i < 8; i++)
        #pragma unroll
        for (int j = 0; j < 8; j++) acc[i][j] = 0.f;

    const int nst = K >> 4;
    #pragma unroll 1
    for (int ks = 0; ks < nst; ks++) {
        // commit staged regs to smem
        #pragma unroll
        for (int u = 0; u < 4; u++) {
            As[lk + u][lr]     = ((const float*)&pa0)[u];
            As[lk + 4 + u][lr] = ((const float*)&pa1)[u];
            Bs[lk + u][lr]     = ((const float*)&pw0)[u];
            Bs[lk + 4 + u][lr] = ((const float*)&pw1)[u];
        }
        __syncthreads();

        if (ks + 1 < nst) {  // prefetch next stage (latency hidden by compute)
            const float* Ap = Aptr + (size_t)(ks + 1) * 16;
            const float* Wp = Wptr + (size_t)(ks + 1) * 16;
            pa0 = *(const float4*)(Ap);
            pa1 = *(const float4*)(Ap + 4);
            pw0 = *(const float4*)(Wp);
            pw1 = *(const float4*)(Wp + 4);
        }

        #pragma unroll
        for (int kk = 0; kk < 16; kk++) {
            float4 a0 = *(const float4*)&As[kk][ty * 4];
            float4 a1 = *(const float4*)&As[kk][ty * 4 + 64];
            float4 b0 = *(const float4*)&Bs[kk][tx * 4];
            float4 b1 = *(const float4*)&Bs[kk][tx * 4 + 64];
            const float av[8] = {a0.x, a0.y, a0.z, a0.w, a1.x, a1.y, a1.z, a1.w};
            const float bv[8] = {b0.x, b0.y, b0.z, b0.w, b1.x, b1.y, b1.z, b1.w};
            #pragma unroll
            for (int i = 0; i < 8; i++)
                #pragma unroll
                for (int j = 0; j < 8; j++)
                    acc[i][j] += av[i] * bv[j];
        }
        __syncthreads();
    }

    // epilogue: + bias, vectorized stores
    #pragma unroll
    for (int i = 0; i < 8; i++) {
        const size_t row = m0 + (size_t)((i >> 2) * 64 + ty * 4 + (i & 3));
        #pragma unroll
        for (int jn = 0; jn < 2; jn++) {
            const size_t col = n0 + (size_t)(jn * 64 + tx * 4);
            const float4 bz = *(const float4*)&bias[col];
            float4 v;
            v.x = acc[i][jn * 4 + 0] + bz.x;
            v.y = acc[i][jn * 4 + 1] + bz.y;
            v.z = acc[i][jn * 4 + 2] + bz.z;
            v.w = acc[i][jn * 4 + 3] + bz.w;
            *(float4*)&C[row * (size_t)N + col] = v;
        }
    }
}

// =====================================================================
// Persistent cluster LSTM scan.
// grid = 128 CTAs = 16 clusters of 8. cluster -> (dir, batch-group of 4).
// CTA rank s owns hidden slice [s*32, s*32+32): 128 W_hh rows (4 gates x 32),
// stored k-major in SMEM (Wt[k][row], conflict-free LDS.128).
// Per step: 8-warp k-split GEMV -> partials -> 128-thread epilogue ->
// h broadcast to cluster peers via DSMEM -> barrier.cluster.
// =====================================================================
#define CLS 8
#define HSL 32
#define BGR 4
#define LSTM_SMEM ((256*128 + 2*BGR*HID + 8*BGR*128) * 4)   // 155648 B

__device__ __forceinline__ float sigm(float x) { return 1.0f / (1.0f + __expf(-x)); }

__global__ void __cluster_dims__(CLS, 1, 1) __launch_bounds__(256, 1)
lstm_scan(const float* __restrict__ xg_f, const float* __restrict__ xg_r,
          const float* __restrict__ Whh_f, const float* __restrict__ Whh_r,
          float* __restrict__ out)
{
    extern __shared__ float sm[];
    float* Wt   = sm;                        // [256][128] k-major
    float* hbuf = sm + 256 * 128;            // [2][BGR][256]
    float* part = hbuf + 2 * BGR * HID;      // [8][BGR][128]

    const int tid   = threadIdx.x;
    const int slice = blockIdx.x & 7;        // cluster rank
    const int cid   = blockIdx.x >> 3;
    const int dir   = cid & 1;
    const int bg    = cid >> 1;              // 0..7

    const float* xg  = dir ? xg_r : xg_f;
    const float* Whh = dir ? Whh_r : Whh_f;

    // ---- load W_hh slice transposed: Wt[k][gate*32+j] = Whh[gate*H + slice*32 + j][k]
    {
        const int r    = tid >> 1;             // 0..127
        const int kh   = (tid & 1) * 128;      // k half
        const int gate = r >> 5;
        const int j    = r & 31;
        const float* src = Whh + (size_t)(gate * HID + slice * HSL + j) * HID + kh;
        #pragma unroll 8
        for (int k4 = 0; k4 < 128; k4 += 4) {
            const float4 w = *(const float4*)(src + k4);
            Wt[(kh + k4 + 0) * 128 + r] = w.x;
            Wt[(kh + k4 + 1) * 128 + r] = w.y;
            Wt[(kh + k4 + 2) * 128 + r] = w.z;
            Wt[(kh + k4 + 3) * 128 + r] = w.w;
        }
    }
    for (int i = tid; i < 2 * BGR * HID; i += 256) hbuf[i] = 0.f;

    asm volatile("barrier.cluster.arrive.aligned;" ::: "memory");
    asm volatile("barrier.cluster.wait.aligned;" ::: "memory");

    const int kc = tid >> 5;   // k-chunk (warp id)
    const int rg = tid & 31;   // row group (4 rows)
    const int eb = tid >> 5;   // epilogue batch (tid<128)
    const int ej = tid & 31;   // epilogue hidden j

    float c_state = 0.f;
    unsigned hloc[2];
    if (tid < 128) {
        hloc[0] = (unsigned)__cvta_generic_to_shared(
            &hbuf[(0 * BGR + eb) * HID + slice * HSL + ej]);
        hloc[1] = (unsigned)__cvta_generic_to_shared(
            &hbuf[(1 * BGR + eb) * HID + slice * HSL + ej]);
    }

    int p = 0;
    #pragma unroll 1
    for (int it = 0; it < SEQT; ++it) {
        const int tt = dir ? (SEQT - 1 - it) : it;

        // prefetch xg gate preactivations (latency hidden under GEMV)
        float xgi = 0.f, xgf = 0.f, xgg = 0.f, xgo = 0.f;
        if (tid < 128) {
            const float* xp = xg + ((size_t)(bg * BGR + eb) * SEQT + tt) * GDIM
                                 + slice * HSL + ej;
            xgi = xp[0];
            xgf = xp[HID];
            xgg = xp[2 * HID];
            xgo = xp[3 * HID];
        }

        // ---- GEMV: acc[r][b] = sum over this warp's 32 k of h[b][k]*Wt[k][4rg+r]
        float acc[4][4];
        #pragma unroll
        for (int r = 0; r < 4; r++)
            #pragma unroll
            for (int b = 0; b < 4; b++) acc[r][b] = 0.f;

        const float* hb = hbuf + (p * BGR) * HID;
        #pragma unroll
        for (int kk = 0; kk < 32; kk += 4) {
            const int k = (kc << 5) + kk;
            const float4 h0 = *(const float4*)(hb + 0 * HID + k);
            const float4 h1 = *(const float4*)(hb + 1 * HID + k);
            const float4 h2 = *(const float4*)(hb + 2 * HID + k);
            const float4 h3 = *(const float4*)(hb + 3 * HID + k);
            #pragma unroll
            for (int u = 0; u < 4; u++) {
                const float4 w = *(const float4*)(Wt + (k + u) * 128 + (rg << 2));
                const float wv[4] = {w.x, w.y, w.z, w.w};
                const float hv[4] = {((const float*)&h0)[u], ((const float*)&h1)[u],
                                     ((const float*)&h2)[u], ((const float*)&h3)[u]};
                #pragma unroll
                for (int r = 0; r < 4; r++)
                    #pragma unroll
                    for (int b = 0; b < 4; b++)
                        acc[r][b] += wv[r] * hv[b];
            }
        }

        #pragma unroll
        for (int r = 0; r < 4; r++)
            #pragma unroll
            for (int b = 0; b < 4; b++)
                part[(kc * BGR + b) * 128 + (rg << 2) + r] = acc[r][b];
        __syncthreads();

        // ---- epilogue: reduce 8 k-chunks, activations, state update, broadcast
        if (tid < 128) {
            float si = xgi, sf = xgf, sg = xgg, so = xgo;
            #pragma unroll
            for (int q = 0; q < 8; q++) {
                const float* pp = part + (q * BGR + eb) * 128 + ej;
                si += pp[0];
                sf += pp[32];
                sg += pp[64];
                so += pp[96];
            }
            const float iv = sigm(si);
            const float fv = sigm(sf);
            const float gv = tanhf(sg);
            const float ov = sigm(so);
            c_state = fv * c_state + iv * gv;
            const float h = ov * tanhf(c_state);

            const unsigned la = hloc[p ^ 1];
            #pragma unroll
            for (int rk = 0; rk < CLS; rk++) {
                unsigned ra;
                asm volatile("mapa.shared::cluster.u32 %0, %1, %2;"
                             : "=r"(ra) : "r"(la), "r"(rk));
                asm volatile("st.shared::cluster.f32 [%0], %1;"
                             :: "r"(ra), "f"(h));
            }
            out[((size_t)(bg * BGR + eb) * SEQT + tt) * (2 * HID)
                + dir * HID + slice * HSL + ej] = h;
        }

        asm volatile("barrier.cluster.arrive.aligned;" ::: "memory");
        asm volatile("barrier.cluster.wait.aligned;" ::: "memory");
        p ^= 1;
    }
}

// =====================================================================
extern "C" void kernel_launch(void* const* d_in, const int* in_sizes, int n_in,
                              void* d_out, int out_size)
{
    const float* x      = (const float*)d_in[0];
    const float* Wih_f0 = (const float*)d_in[1];
    const float* Whh_f0 = (const float*)d_in[2];
    const float* b_f0   = (const float*)d_in[3];
    const float* Wih_r0 = (const float*)d_in[4];
    const float* Whh_r0 = (const float*)d_in[5];
    const float* b_r0   = (const float*)d_in[6];
    const float* Wih_f1 = (const float*)d_in[7];
    const float* Whh_f1 = (const float*)d_in[8];
    const float* b_f1   = (const float*)d_in[9];
    const float* Wih_r1 = (const float*)d_in[10];
    const float* Whh_r1 = (const float*)d_in[11];
    const float* b_r1   = (const float*)d_in[12];
    float* out = (float*)d_out;

    float *xg_f, *xg_r, *h0;
    cudaGetSymbolAddress((void**)&xg_f, g_xg_f);
    cudaGetSymbolAddress((void**)&xg_r, g_xg_r);
    cudaGetSymbolAddress((void**)&h0,  g_h0);

    cudaFuncSetAttribute(lstm_scan, cudaFuncAttributeMaxDynamicSharedMemorySize,
                         LSTM_SMEM);

    dim3 blk(256);
    dim3 grid_g(GDIM / 128, (NBATCH * SEQT) / 128);   // (8, 512)

    // layer 0: input projections + scan
    sgemm_bias<<<grid_g, blk>>>(x, Wih_f0, b_f0, xg_f, DIN);
    sgemm_bias<<<grid_g, blk>>>(x, Wih_r0, b_r0, xg_r, DIN);
    lstm_scan<<<128, blk, LSTM_SMEM>>>(xg_f, xg_r, Whh_f0, Whh_r0, h0);

    // layer 1: input projections over concat(h_f0,h_r0) + scan
    sgemm_bias<<<grid_g, blk>>>(h0, Wih_f1, b_f1, xg_f, 2 * HID);
    sgemm_bias<<<grid_g, blk>>>(h0, Wih_r1, b_r1, xg_r, 2 * HID);
    lstm_scan<<<128, blk, LSTM_SMEM>>>(xg_f, xg_r, Whh_f1, Whh_r1, out);
}

// round 2
// speedup vs baseline: 1.2600x; 1.2600x over previous
#include <cuda_runtime.h>
#include <cstddef>
#include <cstdint>

#define NBATCH 32
#define SEQT   2048
#define DIN    256
#define HID    256
#define GDIM   1024   // 4*HID

// ---------------- scratch (static device allocations, allowed) ----------------
__device__ float g_xg_f[(size_t)NBATCH * SEQT * GDIM];   // 256 MB
__device__ float g_xg_r[(size_t)NBATCH * SEQT * GDIM];   // 256 MB
__device__ float g_h0 [(size_t)NBATCH * SEQT * 2 * HID]; // 128 MB

// ---------------- packed fp32x2 helpers (2 MACs per issue slot) ----------------
__device__ __forceinline__ unsigned long long pack2(float x) {
    unsigned long long r;
    asm("mov.b64 %0, {%1, %1};" : "=l"(r) : "f"(x));
    return r;
}
__device__ __forceinline__ void ffma2(unsigned long long& d,
                                      unsigned long long a, unsigned long long b) {
    asm("fma.rn.f32x2 %0, %1, %2, %0;" : "+l"(d) : "l"(a), "l"(b));
}
__device__ __forceinline__ float2 unpack2(unsigned long long v) {
    float2 f;
    asm("mov.b64 {%0, %1}, %2;" : "=f"(f.x), "=f"(f.y) : "l"(v));
    return f;
}
__device__ __forceinline__ float tanh_fast(float x) {
    float y;
    asm("tanh.approx.f32 %0, %1;" : "=f"(y) : "f"(x));
    return y;
}
__device__ __forceinline__ float sigm(float x) {
    return 0.5f + 0.5f * tanh_fast(0.5f * x);
}

// =====================================================================
// GEMM: C[M,N] = A[M,K] @ W[N,K]^T + bias[N]
// 128x128 tile, BK=16, 256 threads, 8x8 per-thread via fma.rn.f32x2
// =====================================================================
__global__ __launch_bounds__(256, 2)
void sgemm_bias(const float* __restrict__ A, const float* __restrict__ W,
                const float* __restrict__ bias, float* __restrict__ C, int K)
{
    __shared__ float As[16][132];
    __shared__ float Bs[16][132];

    const int tid = threadIdx.x;
    const int tx  = tid & 15;
    const int ty  = tid >> 4;
    const size_t m0 = (size_t)blockIdx.y * 128;
    const size_t n0 = (size_t)blockIdx.x * 128;
    const int N  = gridDim.x * 128;

    const int lr = tid >> 1;          // row in tile 0..127
    const int lk = (tid & 1) * 8;     // k offset 0 or 8

    const float* Aptr = A + (m0 + lr) * (size_t)K + lk;
    const float* Wptr = W + (n0 + lr) * (size_t)K + lk;

    float4 pa0 = *(const float4*)(Aptr);
    float4 pa1 = *(const float4*)(Aptr + 4);
    float4 pw0 = *(const float4*)(Wptr);
    float4 pw1 = *(const float4*)(Wptr + 4);

    unsigned long long acc2[8][4];
    #pragma unroll
    for (int i = 0; i < 8; i++)
        #pragma unroll
        for (int j = 0; j < 4; j++) acc2[i][j] = 0ull;

    const int nst = K >> 4;
    #pragma unroll 1
    for (int ks = 0; ks < nst; ks++) {
        #pragma unroll
        for (int u = 0; u < 4; u++) {
            As[lk + u][lr]     = ((const float*)&pa0)[u];
            As[lk + 4 + u][lr] = ((const float*)&pa1)[u];
            Bs[lk + u][lr]     = ((const float*)&pw0)[u];
            Bs[lk + 4 + u][lr] = ((const float*)&pw1)[u];
        }
        __syncthreads();

        if (ks + 1 < nst) {
            const float* Ap = Aptr + (size_t)(ks + 1) * 16;
            const float* Wp = Wptr + (size_t)(ks + 1) * 16;
            pa0 = *(const float4*)(Ap);
            pa1 = *(const float4*)(Ap + 4);
            pw0 = *(const float4*)(Wp);
            pw1 = *(const float4*)(Wp + 4);
        }

        #pragma unroll
        for (int kk = 0; kk < 16; kk++) {
            float4 a0 = *(const float4*)&As[kk][ty * 4];
            float4 a1 = *(const float4*)&As[kk][ty * 4 + 64];
            ulonglong2 b0 = *(const ulonglong2*)&Bs[kk][tx * 4];
            ulonglong2 b1 = *(const ulonglong2*)&Bs[kk][tx * 4 + 64];
            const unsigned long long bv[4] = {b0.x, b0.y, b1.x, b1.y};
            const float av[8] = {a0.x, a0.y, a0.z, a0.w, a1.x, a1.y, a1.z, a1.w};
            #pragma unroll
            for (int i = 0; i < 8; i++) {
                const unsigned long long ad = pack2(av[i]);
                #pragma unroll
                for (int j = 0; j < 4; j++)
                    ffma2(acc2[i][j], ad, bv[j]);
            }
        }
        __syncthreads();
    }

    // epilogue: + bias, vectorized stores
    #pragma unroll
    for (int i = 0; i < 8; i++) {
        const size_t row = m0 + (size_t)((i >> 2) * 64 + ty * 4 + (i & 3));
        #pragma unroll
        for (int jn = 0; jn < 2; jn++) {
            const size_t col = n0 + (size_t)(jn * 64 + tx * 4);
            const float4 bz = *(const float4*)&bias[col];
            const float2 lo = unpack2(acc2[i][jn * 2 + 0]);
            const float2 hi = unpack2(acc2[i][jn * 2 + 1]);
            float4 v;
            v.x = lo.x + bz.x;
            v.y = lo.y + bz.y;
            v.z = hi.x + bz.z;
            v.w = hi.y + bz.w;
            *(float4*)&C[row * (size_t)N + col] = v;
        }
    }
}

// =====================================================================
// Persistent cluster LSTM scan (f32x2 GEMV inner loop).
// grid = 128 CTAs = 16 clusters of 8. cluster -> (dir, batch-group of 4).
// =====================================================================
#define CLS 8
#define HSL 32
#define BGR 4
#define LSTM_SMEM ((256*128 + 2*BGR*HID + 8*BGR*128) * 4)   // 155648 B

__global__ void __cluster_dims__(CLS, 1, 1) __launch_bounds__(256, 1)
lstm_scan(const float* __restrict__ xg_f, const float* __restrict__ xg_r,
          const float* __restrict__ Whh_f, const float* __restrict__ Whh_r,
          float* __restrict__ out)
{
    extern __shared__ float sm[];
    float* Wt   = sm;                        // [256][128] k-major
    float* hbuf = sm + 256 * 128;            // [2][BGR][256]
    float* part = hbuf + 2 * BGR * HID;      // [8][BGR][128]

    const int tid   = threadIdx.x;
    const int slice = blockIdx.x & 7;        // cluster rank
    const int cid   = blockIdx.x >> 3;
    const int dir   = cid & 1;
    const int bg    = cid >> 1;              // 0..7

    const float* xg  = dir ? xg_r : xg_f;
    const float* Whh = dir ? Whh_r : Whh_f;

    // ---- load W_hh slice transposed: Wt[k][gate*32+j] = Whh[gate*H + slice*32 + j][k]
    {
        const int r    = tid >> 1;
        const int kh   = (tid & 1) * 128;
        const int gate = r >> 5;
        const int j    = r & 31;
        const float* src = Whh + (size_t)(gate * HID + slice * HSL + j) * HID + kh;
        #pragma unroll 8
        for (int k4 = 0; k4 < 128; k4 += 4) {
            const float4 w = *(const float4*)(src + k4);
            Wt[(kh + k4 + 0) * 128 + r] = w.x;
            Wt[(kh + k4 + 1) * 128 + r] = w.y;
            Wt[(kh + k4 + 2) * 128 + r] = w.z;
            Wt[(kh + k4 + 3) * 128 + r] = w.w;
        }
    }
    for (int i = tid; i < 2 * BGR * HID; i += 256) hbuf[i] = 0.f;

    asm volatile("barrier.cluster.arrive.aligned;" ::: "memory");
    asm volatile("barrier.cluster.wait.aligned;" ::: "memory");

    const int kc = tid >> 5;   // k-chunk (warp id)
    const int rg = tid & 31;   // row group (4 rows)
    const int eb = tid >> 5;   // epilogue batch (tid<128)
    const int ej = tid & 31;   // epilogue hidden j

    float c_state = 0.f;
    unsigned hloc[2];
    if (tid < 128) {
        hloc[0] = (unsigned)__cvta_generic_to_shared(
            &hbuf[(0 * BGR + eb) * HID + slice * HSL + ej]);
        hloc[1] = (unsigned)__cvta_generic_to_shared(
            &hbuf[(1 * BGR + eb) * HID + slice * HSL + ej]);
    }

    int p = 0;
    #pragma unroll 1
    for (int it = 0; it < SEQT; ++it) {
        const int tt = dir ? (SEQT - 1 - it) : it;

        // prefetch xg gate preactivations (latency hidden under GEMV)
        float xgi = 0.f, xgf = 0.f, xgg = 0.f, xgo = 0.f;
        if (tid < 128) {
            const float* xp = xg + ((size_t)(bg * BGR + eb) * SEQT + tt) * GDIM
                                 + slice * HSL + ej;
            xgi = xp[0];
            xgf = xp[HID];
            xgg = xp[2 * HID];
            xgo = xp[3 * HID];
        }

        // ---- GEMV via f32x2: acc2[rp][b] holds rows (4rg+2rp, 4rg+2rp+1)
        unsigned long long acc2[2][4];
        #pragma unroll
        for (int rp = 0; rp < 2; rp++)
            #pragma unroll
            for (int b = 0; b < 4; b++) acc2[rp][b] = 0ull;

        const float* hb = hbuf + (p * BGR) * HID;
        #pragma unroll
        for (int kk = 0; kk < 32; kk += 4) {
            const int k = (kc << 5) + kk;
            const float4 h0 = *(const float4*)(hb + 0 * HID + k);
            const float4 h1 = *(const float4*)(hb + 1 * HID + k);
            const float4 h2 = *(const float4*)(hb + 2 * HID + k);
            const float4 h3 = *(const float4*)(hb + 3 * HID + k);
            #pragma unroll
            for (int u = 0; u < 4; u++) {
                const ulonglong2 wp =
                    *(const ulonglong2*)(Wt + (k + u) * 128 + (rg << 2));
                const unsigned long long hd[4] = {
                    pack2(((const float*)&h0)[u]), pack2(((const float*)&h1)[u]),
                    pack2(((const float*)&h2)[u]), pack2(((const float*)&h3)[u])};
                #pragma unroll
                for (int b = 0; b < 4; b++) {
                    ffma2(acc2[0][b], wp.x, hd[b]);
                    ffma2(acc2[1][b], wp.y, hd[b]);
                }
            }
        }

        #pragma unroll
        for (int b = 0; b < 4; b++) {
            float* pp = part + (kc * BGR + b) * 128 + (rg << 2);
            *(unsigned long long*)(pp)     = acc2[0][b];
            *(unsigned long long*)(pp + 2) = acc2[1][b];
        }
        __syncthreads();

        // ---- epilogue: reduce 8 k-chunks, activations, state update, broadcast
        float h = 0.f;
        if (tid < 128) {
            float si = xgi, sf = xgf, sg = xgg, so = xgo;
            #pragma unroll
            for (int q = 0; q < 8; q++) {
                const float* pp = part + (q * BGR + eb) * 128 + ej;
                si += pp[0];
                sf += pp[32];
                sg += pp[64];
                so += pp[96];
            }
            const float iv = sigm(si);
            const float fv = sigm(sf);
            const float gv = tanh_fast(sg);
            const float ov = sigm(so);
            c_state = fv * c_state + iv * gv;
            h = ov * tanh_fast(c_state);

            const unsigned la = hloc[p ^ 1];
            #pragma unroll
            for (int rk = 0; rk < CLS; rk++) {
                unsigned ra;
                asm volatile("mapa.shared::cluster.u32 %0, %1, %2;"
                             : "=r"(ra) : "r"(la), "r"(rk));
                asm volatile("st.shared::cluster.f32 [%0], %1;"
                             :: "r"(ra), "f"(h));
            }
        }

        asm volatile("barrier.cluster.arrive.aligned;" ::: "memory");
        if (tid < 128) {   // hide STG behind the cluster-barrier wait
            out[((size_t)(bg * BGR + eb) * SEQT + tt) * (2 * HID)
                + dir * HID + slice * HSL + ej] = h;
        }
        asm volatile("barrier.cluster.wait.aligned;" ::: "memory");
        p ^= 1;
    }
}

// =====================================================================
extern "C" void kernel_launch(void* const* d_in, const int* in_sizes, int n_in,
                              void* d_out, int out_size)
{
    const float* x      = (const float*)d_in[0];
    const float* Wih_f0 = (const float*)d_in[1];
    const float* Whh_f0 = (const float*)d_in[2];
    const float* b_f0   = (const float*)d_in[3];
    const float* Wih_r0 = (const float*)d_in[4];
    const float* Whh_r0 = (const float*)d_in[5];
    const float* b_r0   = (const float*)d_in[6];
    const float* Wih_f1 = (const float*)d_in[7];
    const float* Whh_f1 = (const float*)d_in[8];
    const float* b_f1   = (const float*)d_in[9];
    const float* Wih_r1 = (const float*)d_in[10];
    const float* Whh_r1 = (const float*)d_in[11];
    const float* b_r1   = (const float*)d_in[12];
    float* out = (float*)d_out;

    float *xg_f, *xg_r, *h0;
    cudaGetSymbolAddress((void**)&xg_f, g_xg_f);
    cudaGetSymbolAddress((void**)&xg_r, g_xg_r);
    cudaGetSymbolAddress((void**)&h0,  g_h0);

    cudaFuncSetAttribute(lstm_scan, cudaFuncAttributeMaxDynamicSharedMemorySize,
                         LSTM_SMEM);

    dim3 blk(256);
    dim3 grid_g(GDIM / 128, (NBATCH * SEQT) / 128);   // (8, 512)

    // layer 0: input projections + scan
    sgemm_bias<<<grid_g, blk>>>(x, Wih_f0, b_f0, xg_f, DIN);
    sgemm_bias<<<grid_g, blk>>>(x, Wih_r0, b_r0, xg_r, DIN);
    lstm_scan<<<128, blk, LSTM_SMEM>>>(xg_f, xg_r, Whh_f0, Whh_r0, h0);

    // layer 1: input projections over concat(h_f0,h_r0) + scan
    sgemm_bias<<<grid_g, blk>>>(h0, Wih_f1, b_f1, xg_f, 2 * HID);
    sgemm_bias<<<grid_g, blk>>>(h0, Wih_r1, b_r1, xg_r, 2 * HID);
    lstm_scan<<<128, blk, LSTM_SMEM>>>(xg_f, xg_r, Whh_f1, Whh_r1, out);
}